// round 2
// baseline (speedup 1.0000x reference)
#include <cuda_runtime.h>
#include <math.h>

// MT 1D forward + loss. 16384 frequencies x 255-layer serial recursion.
// Homogeneous (division-free) Mobius form of the impedance recursion:
//   Z' = Zj*((1-E)Z + Zj(1+E)) / ((1+E)Z + Zj(1-E)),  E = exp(-2kt)
// With Z = P/Q:
//   P' = a*P + b*Q ; Q' = g*P + a*Q
//   a = Zj*(1-E), b = Zj^2*(1+E) = i*omu*rho*(1+E), g = (1+E)
// Exact power-of-2 renorm every 8 steps keeps fp32 in range.

#define MU_F 1.2566370614359173e-6f
#define TWO_PI_F 6.283185307179586f
#define RSQRT2_F 0.7071067811865476f
#define SQRT2_F 1.4142135623730951f
#define RAD2DEG_F 57.29577951308232f

static __device__ float2 g_part[1024];

__global__ __launch_bounds__(128) void mt_main(
    const float* __restrict__ rho, const float* __restrict__ thick,
    const float* __restrict__ freq, const float* __restrict__ obs_r,
    const float* __restrict__ obs_p, int nz, int nf)
{
    // Packed per-layer constants: x = sqrt(rho_j)/sqrt2 (-> Zv = s*x)
    //                             y = sqrt2*t_j/sqrt(rho_j) (-> arg = s*y)
    //                             z = rho_j (-> |b| = omu*z), w unused
    __shared__ float4 sL[512];
    __shared__ float s_qlast;

    const int tid = threadIdx.x;
    for (int j = tid; j < nz - 1; j += blockDim.x) {
        float r = rho[j];
        float q = sqrtf(r);
        sL[j] = make_float4(q * RSQRT2_F, SQRT2_F * thick[j] / q, r, 0.f);
    }
    if (tid == 0) s_qlast = sqrtf(rho[nz - 1]) * RSQRT2_F;
    __syncthreads();

    const int i = blockIdx.x * blockDim.x + tid;
    float t1 = 0.f, t2 = 0.f;
    if (i < nf) {
        const float omu = TWO_PI_F * freq[i] * MU_F;  // omega*MU
        const float s = sqrtf(omu);                   // sqrt(omega*MU)
        const float Zv0 = s * s_qlast;
        // Z0 = Zv0*(1+i); homogeneous state (P, Q), Z = P/Q
        float Pre = Zv0, Pim = Zv0, Qre = 1.f, Qim = 0.f;

        #pragma unroll 4
        for (int j = nz - 2; j >= 0; --j) {
            float4 L = sL[j];
            float arg = s * L.y;
            float e = __expf(-arg);
            float sn, cs;
            __sincosf(arg, &sn, &cs);
            float ec = e * cs;           // Re(E)
            float es = e * sn;           // -Im(E) ; E = ec - i*es
            float Zv = s * L.x;          // Zj = Zv*(1+i)
            float tv = omu * L.z;        // = 2*Zv^2
            float u = 1.f - ec;          // Re(1-E); Im(1-E) = es
            float v = 1.f + ec;          // Re(1+E); Im(1+E) = -es
            // a = Zj*(1-E) = Zv*((u-es) + i(u+es))
            float are = Zv * (u - es);
            float aim = Zv * (u + es);
            // b = Zj^2*(1+E) = i*tv*(v - i*es) = tv*(es + i*v)
            float bre = tv * es;
            float bim = tv * v;
            // g = (1+E) = (v, -es)
            float nPre = are * Pre - aim * Pim + bre * Qre - bim * Qim;
            float nPim = are * Pim + aim * Pre + bre * Qim + bim * Qre;
            float nQre = v   * Pre + es  * Pim + are * Qre - aim * Qim;
            float nQim = v   * Pim - es  * Pre + are * Qim + aim * Qre;

            if ((j & 7) == 0) {
                // exact pow2 renorm so |Q| ~ 1 (no rounding perturbation)
                float m = fmaxf(fmaxf(fabsf(nQre), fabsf(nQim)), 1e-30f);
                unsigned eb = __float_as_uint(m) & 0x7f800000u;
                float sc = __uint_as_float(0x7f000000u - eb);
                nPre *= sc; nPim *= sc; nQre *= sc; nQim *= sc;
            }
            Pre = nPre; Pim = nPim; Qre = nQre; Qim = nQim;
        }

        // Z = P/Q (single complex division, off the hot loop)
        float den = Qre * Qre + Qim * Qim;
        float inv = 1.f / den;
        float Zre = (Pre * Qre + Pim * Qim) * inv;
        float Zim = (Pim * Qre - Pre * Qim) * inv;

        float app_res = (Zre * Zre + Zim * Zim) / omu;
        float dl = log10f(app_res) - log10f(obs_r[i]);
        t1 = dl * dl;
        float ph = atan2f(Zim, Zre) * RAD2DEG_F;
        float dp = ph - obs_p[i];
        t2 = dp * dp;
    }

    // deterministic block reduction (warp shuffle tree + shared)
    float x = t1, y = t2;
    #pragma unroll
    for (int o = 16; o > 0; o >>= 1) {
        x += __shfl_down_sync(0xffffffffu, x, o);
        y += __shfl_down_sync(0xffffffffu, y, o);
    }
    __shared__ float2 ws[4];
    int w = tid >> 5, l = tid & 31;
    if (l == 0) ws[w] = make_float2(x, y);
    __syncthreads();
    if (w == 0) {
        float2 vv = (l < ((int)blockDim.x >> 5)) ? ws[l] : make_float2(0.f, 0.f);
        #pragma unroll
        for (int o = 2; o > 0; o >>= 1) {
            vv.x += __shfl_down_sync(0xffffffffu, vv.x, o);
            vv.y += __shfl_down_sync(0xffffffffu, vv.y, o);
        }
        if (l == 0) g_part[blockIdx.x] = vv;
    }
}

__global__ void mt_fin(float* __restrict__ out, int nblocks, float invnf)
{
    float x = 0.f, y = 0.f;
    for (int b = threadIdx.x; b < nblocks; b += 32) {
        float2 p = g_part[b];
        x += p.x; y += p.y;
    }
    #pragma unroll
    for (int o = 16; o > 0; o >>= 1) {
        x += __shfl_down_sync(0xffffffffu, x, o);
        y += __shfl_down_sync(0xffffffffu, y, o);
    }
    if (threadIdx.x == 0) {
        float lr = x * invnf;
        float lp = y * invnf;
        out[0] = lr + 10.f * lp;   // total_loss
        out[1] = lr;               // loss_rhoa
        out[2] = lp;               // loss_phase
    }
}

extern "C" void kernel_launch(void* const* d_in, const int* in_sizes, int n_in,
                              void* d_out, int out_size)
{
    const float* rho    = (const float*)d_in[0];
    const float* thick  = (const float*)d_in[1];
    const float* freq   = (const float*)d_in[2];
    const float* obs_r  = (const float*)d_in[3];
    const float* obs_p  = (const float*)d_in[4];
    int nz = in_sizes[0];
    int nf = in_sizes[2];
    int blocks = (nf + 127) / 128;
    if (blocks > 1024) blocks = 1024;  // g_part capacity (nf=16384 -> 128)
    mt_main<<<blocks, 128>>>(rho, thick, freq, obs_r, obs_p, nz, nf);
    mt_fin<<<1, 32>>>((float*)d_out, blocks, 1.f / (float)nf);
}

// round 3
// speedup vs baseline: 1.2035x; 1.2035x over previous
#include <cuda_runtime.h>
#include <math.h>

// MT 1D forward + loss, single fused kernel.
// Homogeneous (division-free) Mobius form of the impedance recursion:
//   Z' = Zj*((1-E)Z + Zj(1+E)) / ((1+E)Z + Zj(1-E)),  E = exp(-2kt)
// With Z = P/Q:  P' = a*P + b*Q ; Q' = g*P + a*Q
//   a = Zj*(1-E), b = Zj^2*(1+E) = i*omu*rho*(1+E), g = (1+E)
// Coefficients are state-independent -> software-pipelined in branchless
// blocks of 8 steps; exact pow2 renorm between blocks (cancels in P/Q).
// Final loss reduction fused via fence + atomic ticket (last block reduces,
// then resets the ticket so graph replays stay deterministic).

#define MU_F 1.2566370614359173e-6f
#define TWO_PI_F 6.283185307179586f
#define RSQRT2_F 0.7071067811865476f
#define SQRT2_F 1.4142135623730951f
#define RAD2DEG_F 57.29577951308232f
#define NLOG2E_F (-1.4426950408889634f)

static __device__ float2 g_part[1024];
static __device__ unsigned g_ticket;   // zero-init; last block resets to 0

struct St { float Pre, Pim, Qre, Qim; };

__device__ __forceinline__ void mt_step(St& S, float s, float omu, float4 L)
{
    // L.x = sqrt(rho)/sqrt2, L.y = sqrt2*t/sqrt(rho), L.z = rho, L.w = -log2e*L.y
    float arg = s * L.y;
    float e;
    asm("ex2.approx.ftz.f32 %0, %1;" : "=f"(e) : "f"(s * L.w));  // exp(-arg)
    float sn, cs;
    __sincosf(arg, &sn, &cs);
    float ec = e * cs;              // Re(E)
    float es = e * sn;              // -Im(E); E = ec - i*es
    float Zv = s * L.x;             // Zj = Zv*(1+i)
    float tv = omu * L.z;           // = 2*Zv^2
    float u = 1.f - ec;
    float v = 1.f + ec;
    float are = Zv * (u - es);
    float aim = Zv * (u + es);
    float bre = tv * es;
    float bim = tv * v;
    float nPre = are * S.Pre - aim * S.Pim + bre * S.Qre - bim * S.Qim;
    float nPim = are * S.Pim + aim * S.Pre + bre * S.Qim + bim * S.Qre;
    float nQre = v   * S.Pre + es  * S.Pim + are * S.Qre - aim * S.Qim;
    float nQim = v   * S.Pim - es  * S.Pre + are * S.Qim + aim * S.Qre;
    S.Pre = nPre; S.Pim = nPim; S.Qre = nQre; S.Qim = nQim;
}

__device__ __forceinline__ void renorm(St& S)
{
    // exact power-of-2 rescale so |Q| ~ 1 (cancels exactly in Z = P/Q)
    float m = fmaxf(fmaxf(fabsf(S.Qre), fabsf(S.Qim)), 1e-30f);
    unsigned eb = __float_as_uint(m) & 0x7f800000u;
    float sc = __uint_as_float(0x7f000000u - eb);
    S.Pre *= sc; S.Pim *= sc; S.Qre *= sc; S.Qim *= sc;
}

__global__ __launch_bounds__(128) void mt_fused(
    const float* __restrict__ rho, const float* __restrict__ thick,
    const float* __restrict__ freq, const float* __restrict__ obs_r,
    const float* __restrict__ obs_p, float* __restrict__ out,
    int nz, int nf, float invnf)
{
    __shared__ float4 sL[512];
    __shared__ float s_qlast;
    __shared__ int s_last;

    const int tid = threadIdx.x;
    for (int j = tid; j < nz - 1; j += blockDim.x) {
        float r = rho[j];
        float q = sqrtf(r);
        float T = SQRT2_F * thick[j] / q;
        sL[j] = make_float4(q * RSQRT2_F, T, r, NLOG2E_F * T);
    }
    if (tid == 0) s_qlast = sqrtf(rho[nz - 1]) * RSQRT2_F;
    __syncthreads();

    const int i = blockIdx.x * blockDim.x + tid;
    float t1 = 0.f, t2 = 0.f;
    if (i < nf) {
        const float omu = TWO_PI_F * freq[i] * MU_F;
        const float s = sqrtf(omu);
        const float Zv0 = s * s_qlast;
        St S; S.Pre = Zv0; S.Pim = Zv0; S.Qre = 1.f; S.Qim = 0.f;  // Z0 = Zv0*(1+i)

        int j = nz - 2;                 // first step index (bottom-up)
        int rem = (nz - 1) & 7;         // peel remainder so bulk is blocks of 8
        for (int k = 0; k < rem; ++k) { mt_step(S, s, omu, sL[j]); --j; }
        renorm(S);
        while (j >= 7) {
            #pragma unroll
            for (int k = 0; k < 8; ++k) mt_step(S, s, omu, sL[j - k]);
            j -= 8;
            renorm(S);
        }

        // Z = P/Q (single division, off the hot loop)
        float den = S.Qre * S.Qre + S.Qim * S.Qim;
        float inv = 1.f / den;
        float Zre = (S.Pre * S.Qre + S.Pim * S.Qim) * inv;
        float Zim = (S.Pim * S.Qre - S.Pre * S.Qim) * inv;

        float app_res = (Zre * Zre + Zim * Zim) / omu;
        float dl = log10f(app_res) - log10f(obs_r[i]);
        t1 = dl * dl;
        float ph = atan2f(Zim, Zre) * RAD2DEG_F;
        float dp = ph - obs_p[i];
        t2 = dp * dp;
    }

    // deterministic block reduction
    float x = t1, y = t2;
    #pragma unroll
    for (int o = 16; o > 0; o >>= 1) {
        x += __shfl_down_sync(0xffffffffu, x, o);
        y += __shfl_down_sync(0xffffffffu, y, o);
    }
    __shared__ float2 ws[4];
    int w = tid >> 5, l = tid & 31;
    if (l == 0) ws[w] = make_float2(x, y);
    __syncthreads();
    if (w == 0) {
        float2 vv = (l < ((int)blockDim.x >> 5)) ? ws[l] : make_float2(0.f, 0.f);
        #pragma unroll
        for (int o = 2; o > 0; o >>= 1) {
            vv.x += __shfl_down_sync(0xffffffffu, vv.x, o);
            vv.y += __shfl_down_sync(0xffffffffu, vv.y, o);
        }
        if (l == 0) g_part[blockIdx.x] = vv;
    }

    // last-block final reduction (fence + ticket; ticket reset keeps graph
    // replays deterministic)
    __threadfence();
    if (tid == 0) {
        unsigned t = atomicAdd(&g_ticket, 1u);
        s_last = (t == gridDim.x - 1u);
    }
    __syncthreads();
    if (s_last) {
        int nb = gridDim.x;
        float fx = 0.f, fy = 0.f;
        for (int b = tid; b < nb; b += blockDim.x) {
            float2 p = g_part[b];
            fx += p.x; fy += p.y;
        }
        #pragma unroll
        for (int o = 16; o > 0; o >>= 1) {
            fx += __shfl_down_sync(0xffffffffu, fx, o);
            fy += __shfl_down_sync(0xffffffffu, fy, o);
        }
        __shared__ float2 ws2[4];
        if (l == 0) ws2[w] = make_float2(fx, fy);
        __syncthreads();
        if (tid == 0) {
            float gx = 0.f, gy = 0.f;
            int nw = (int)blockDim.x >> 5;
            for (int q = 0; q < nw; ++q) { gx += ws2[q].x; gy += ws2[q].y; }
            float lr = gx * invnf;
            float lp = gy * invnf;
            out[0] = lr + 10.f * lp;
            out[1] = lr;
            out[2] = lp;
            g_ticket = 0u;   // reset for next graph replay
        }
    }
}

extern "C" void kernel_launch(void* const* d_in, const int* in_sizes, int n_in,
                              void* d_out, int out_size)
{
    const float* rho    = (const float*)d_in[0];
    const float* thick  = (const float*)d_in[1];
    const float* freq   = (const float*)d_in[2];
    const float* obs_r  = (const float*)d_in[3];
    const float* obs_p  = (const float*)d_in[4];
    int nz = in_sizes[0];
    int nf = in_sizes[2];
    int blocks = (nf + 127) / 128;
    if (blocks > 1024) blocks = 1024;  // g_part capacity (nf=16384 -> 128)
    mt_fused<<<blocks, 128>>>(rho, thick, freq, obs_r, obs_p,
                              (float*)d_out, nz, nf, 1.f / (float)nf);
}

// round 4
// speedup vs baseline: 1.2222x; 1.0156x over previous
#include <cuda_runtime.h>
#include <math.h>

// MT 1D forward + loss, single fused kernel.
// Homogeneous (division-free) Mobius form of the impedance recursion:
//   Z' = Zj*((1-E)Z + Zj(1+E)) / ((1+E)Z + Zj(1-E)),  E = exp(-2kt)
// With Z = P/Q:  P' = a*P + b*Q ; Q' = g*P + a*Q
//   a = Zj*(1-E), b = Zj^2*(1+E) = i*omu*rho*(1+E), g = (1+E) = (v, -es)
// Coefficients are state-independent. The inner loop is blocks of 8 steps:
// phase A computes all 8 coefficient sets (independent -> MUFU/FMA pipelined),
// phase B applies the 8 serial state updates. __launch_bounds__(128,1) frees
// the register budget so ptxas can actually software-pipeline this.
// Exact pow2 renorm between blocks (cancels exactly in P/Q).
// Loss reduction fused via fence + atomic ticket (ticket reset on use so
// graph replays stay deterministic).

#define MU_F 1.2566370614359173e-6f
#define TWO_PI_F 6.283185307179586f
#define RSQRT2_F 0.7071067811865476f
#define SQRT2_F 1.4142135623730951f
#define RAD2DEG_F 57.29577951308232f
#define NLOG2E_F (-1.4426950408889634f)

static __device__ float2 g_part[1024];
static __device__ unsigned g_ticket;   // zero-init; last block resets to 0

struct Coef { float are, aim, bre, bim, v, es; };

__device__ __forceinline__ Coef mk_coef(float s, float omu, float4 L)
{
    // L.x = sqrt(rho)/sqrt2, L.y = sqrt2*t/sqrt(rho), L.z = rho, L.w = -log2e*L.y
    Coef c;
    float arg = s * L.y;
    float e;
    asm("ex2.approx.ftz.f32 %0, %1;" : "=f"(e) : "f"(s * L.w));  // exp(-arg)
    float sn, cs;
    __sincosf(arg, &sn, &cs);
    float ec = e * cs;               // Re(E)
    c.es = e * sn;                   // -Im(E); E = ec - i*es
    float Zv = s * L.x;              // Zj = Zv*(1+i)
    float tv = omu * L.z;            // = 2*Zv^2
    float u = 1.f - ec;
    c.v = 1.f + ec;
    c.are = Zv * (u - c.es);
    c.aim = Zv * (u + c.es);
    c.bre = tv * c.es;
    c.bim = tv * c.v;
    return c;
}

struct St { float Pre, Pim, Qre, Qim; };

__device__ __forceinline__ void apply(St& S, const Coef& c)
{
    float nPre = c.are * S.Pre - c.aim * S.Pim + c.bre * S.Qre - c.bim * S.Qim;
    float nPim = c.are * S.Pim + c.aim * S.Pre + c.bre * S.Qim + c.bim * S.Qre;
    float nQre = c.v   * S.Pre + c.es  * S.Pim + c.are * S.Qre - c.aim * S.Qim;
    float nQim = c.v   * S.Pim - c.es  * S.Pre + c.are * S.Qim + c.aim * S.Qre;
    S.Pre = nPre; S.Pim = nPim; S.Qre = nQre; S.Qim = nQim;
}

__device__ __forceinline__ void renorm(St& S)
{
    // exact power-of-2 rescale so |Q| ~ 1 (cancels exactly in Z = P/Q)
    float m = fmaxf(fmaxf(fabsf(S.Qre), fabsf(S.Qim)), 1e-30f);
    unsigned eb = __float_as_uint(m) & 0x7f800000u;
    float sc = __uint_as_float(0x7f000000u - eb);
    S.Pre *= sc; S.Pim *= sc; S.Qre *= sc; S.Qim *= sc;
}

__global__ __launch_bounds__(128, 1) void mt_fused(
    const float* __restrict__ rho, const float* __restrict__ thick,
    const float* __restrict__ freq, const float* __restrict__ obs_r,
    const float* __restrict__ obs_p, float* __restrict__ out,
    int nz, int nf, float invnf)
{
    __shared__ float4 sL[512];
    __shared__ float s_qlast;
    __shared__ int s_last;

    const int tid = threadIdx.x;
    for (int j = tid; j < nz - 1; j += blockDim.x) {
        float r = rho[j];
        float q = sqrtf(r);
        float T = SQRT2_F * thick[j] / q;
        sL[j] = make_float4(q * RSQRT2_F, T, r, NLOG2E_F * T);
    }
    if (tid == 0) s_qlast = sqrtf(rho[nz - 1]) * RSQRT2_F;
    __syncthreads();

    const int i = blockIdx.x * blockDim.x + tid;
    float t1 = 0.f, t2 = 0.f;
    if (i < nf) {
        const float omu = TWO_PI_F * freq[i] * MU_F;
        const float s = sqrtf(omu);
        const float Zv0 = s * s_qlast;
        St S; S.Pre = Zv0; S.Pim = Zv0; S.Qre = 1.f; S.Qim = 0.f;  // Z0 = Zv0*(1+i)

        int j = nz - 2;                 // first step index (bottom-up)
        int rem = (nz - 1) & 7;         // peel remainder so bulk is blocks of 8
        for (int k = 0; k < rem; ++k) { apply(S, mk_coef(s, omu, sL[j])); --j; }
        renorm(S);
        while (j >= 7) {
            Coef c[8];
            // Phase A: 8 independent coefficient sets (pipelines MUFUs)
            #pragma unroll
            for (int k = 0; k < 8; ++k) c[k] = mk_coef(s, omu, sL[j - k]);
            // Phase B: 8 serial state updates (4 independent depth-4 chains)
            #pragma unroll
            for (int k = 0; k < 8; ++k) apply(S, c[k]);
            j -= 8;
            renorm(S);
        }

        // Z = P/Q (single division, off the hot loop)
        float den = S.Qre * S.Qre + S.Qim * S.Qim;
        float inv = 1.f / den;
        float Zre = (S.Pre * S.Qre + S.Pim * S.Qim) * inv;
        float Zim = (S.Pim * S.Qre - S.Pre * S.Qim) * inv;

        float app_res = (Zre * Zre + Zim * Zim) / omu;
        float dl = log10f(app_res) - log10f(obs_r[i]);
        t1 = dl * dl;
        float ph = atan2f(Zim, Zre) * RAD2DEG_F;
        float dp = ph - obs_p[i];
        t2 = dp * dp;
    }

    // deterministic block reduction
    float x = t1, y = t2;
    #pragma unroll
    for (int o = 16; o > 0; o >>= 1) {
        x += __shfl_down_sync(0xffffffffu, x, o);
        y += __shfl_down_sync(0xffffffffu, y, o);
    }
    __shared__ float2 ws[4];
    int w = tid >> 5, l = tid & 31;
    if (l == 0) ws[w] = make_float2(x, y);
    __syncthreads();
    if (w == 0) {
        float2 vv = (l < ((int)blockDim.x >> 5)) ? ws[l] : make_float2(0.f, 0.f);
        #pragma unroll
        for (int o = 2; o > 0; o >>= 1) {
            vv.x += __shfl_down_sync(0xffffffffu, vv.x, o);
            vv.y += __shfl_down_sync(0xffffffffu, vv.y, o);
        }
        if (l == 0) g_part[blockIdx.x] = vv;
    }

    // last-block final reduction (fence + ticket; ticket reset keeps graph
    // replays deterministic)
    __threadfence();
    if (tid == 0) {
        unsigned t = atomicAdd(&g_ticket, 1u);
        s_last = (t == gridDim.x - 1u);
    }
    __syncthreads();
    if (s_last) {
        int nb = gridDim.x;
        float fx = 0.f, fy = 0.f;
        for (int b = tid; b < nb; b += blockDim.x) {
            float2 p = g_part[b];
            fx += p.x; fy += p.y;
        }
        #pragma unroll
        for (int o = 16; o > 0; o >>= 1) {
            fx += __shfl_down_sync(0xffffffffu, fx, o);
            fy += __shfl_down_sync(0xffffffffu, fy, o);
        }
        __shared__ float2 ws2[4];
        if (l == 0) ws2[w] = make_float2(fx, fy);
        __syncthreads();
        if (tid == 0) {
            float gx = 0.f, gy = 0.f;
            int nw = (int)blockDim.x >> 5;
            for (int q = 0; q < nw; ++q) { gx += ws2[q].x; gy += ws2[q].y; }
            float lr = gx * invnf;
            float lp = gy * invnf;
            out[0] = lr + 10.f * lp;
            out[1] = lr;
            out[2] = lp;
            g_ticket = 0u;   // reset for next graph replay
        }
    }
}

extern "C" void kernel_launch(void* const* d_in, const int* in_sizes, int n_in,
                              void* d_out, int out_size)
{
    const float* rho    = (const float*)d_in[0];
    const float* thick  = (const float*)d_in[1];
    const float* freq   = (const float*)d_in[2];
    const float* obs_r  = (const float*)d_in[3];
    const float* obs_p  = (const float*)d_in[4];
    int nz = in_sizes[0];
    int nf = in_sizes[2];
    int blocks = (nf + 127) / 128;
    if (blocks > 1024) blocks = 1024;  // g_part capacity (nf=16384 -> 128)
    mt_fused<<<blocks, 128>>>(rho, thick, freq, obs_r, obs_p,
                              (float*)d_out, nz, nf, 1.f / (float)nf);
}

// round 5
// speedup vs baseline: 1.3601x; 1.1128x over previous
#include <cuda_runtime.h>
#include <math.h>

// MT 1D forward + loss, single fused kernel — diagonalized recursion.
// Normalize Z to each layer's intrinsic impedance: y = Z/Zj. In the basis
// S = y+1, D = y−1 the reference step
//   y' = (y(1−E) + (1+E)) / (y(1+E) + (1−E)),  E = exp(−2 k_j t_j)
// is diagonal (S'=S, D'=−E·D); the only mixing is the inter-layer
// renormalization y ← y·w,  w = sqrt(rho_j/rho_{j−1}) (REAL, precomputed):
//   T = E·D ; S' = p·S − m·T ; D' = m·S − p·T,  p=(w+1)/2, m=(w−1)/2.
// 16 FMA-pipe ops + 3 MUFU per step (vs ~35 before).
// Final: Z = y·Z_L0, |Z_L0|^2 = omu*rho0, arg(Z_L0) = 45 deg exactly.
// Exact pow2 renorm every 8 steps (cancels in the S/D ratio).
// Loss reduction fused via fence + atomic ticket (reset for graph replay).

#define MU_F 1.2566370614359173e-6f
#define TWO_PI_F 6.283185307179586f
#define SQRT2_F 1.4142135623730951f
#define RAD2DEG_F 57.29577951308232f
#define NLOG2E_F (-1.4426950408889634f)

static __device__ float2 g_part[1024];
static __device__ unsigned g_ticket;   // zero-init; last block resets to 0

__global__ __launch_bounds__(128, 1) void mt_fused(
    const float* __restrict__ rho, const float* __restrict__ thick,
    const float* __restrict__ freq, const float* __restrict__ obs_r,
    const float* __restrict__ obs_p, float* __restrict__ out,
    int nz, int nf, float invnf)
{
    // Per-layer record: x = sqrt2*t_j/sqrt(rho_j)      (arg = s*x)
    //                   y = -log2e * x                 (e = ex2(s*y))
    //                   z = p_j = (w_j+1)/2, w = m_j = (w_j-1)/2
    //                   w_j = sqrt(rho_j/rho_{j-1}) (j>0), w_0 = 1
    __shared__ float4 sL[512];
    __shared__ float s_y0;     // initial y = sqrt(rho[nz-1]/rho[nz-2]) (real)
    __shared__ float s_rho0;
    __shared__ int s_last;

    const int tid = threadIdx.x;
    for (int j = tid; j < nz - 1; j += blockDim.x) {
        float r = rho[j];
        float T = SQRT2_F * thick[j] * rsqrtf(r);
        float w = (j > 0) ? sqrtf(r / rho[j - 1]) : 1.0f;
        sL[j] = make_float4(T, NLOG2E_F * T, 0.5f * (w + 1.f), 0.5f * (w - 1.f));
    }
    if (tid == 0) {
        s_y0 = sqrtf(rho[nz - 1] / rho[nz - 2]);
        s_rho0 = rho[0];
    }
    __syncthreads();

    const int i = blockIdx.x * blockDim.x + tid;
    float t1 = 0.f, t2 = 0.f;
    if (i < nf) {
        const float omu = TWO_PI_F * freq[i] * MU_F;
        const float s = sqrtf(omu);
        const float y0 = s_y0;
        float Sre = y0 + 1.f, Sim = 0.f;   // S = y + 1
        float Dre = y0 - 1.f, Dim = 0.f;   // D = y - 1

        int j = nz - 2;
        int rem = (nz - 1) & 7;            // peel so bulk is blocks of 8
        #pragma unroll 1
        for (int k = 0; k < rem; ++k, --j) {
            float4 L = sL[j];
            float arg = s * L.x;
            float e; asm("ex2.approx.ftz.f32 %0, %1;" : "=f"(e) : "f"(s * L.y));
            float sn, cs; __sincosf(arg, &sn, &cs);
            float ec = e * cs, es = e * sn;        // E = ec - i*es
            float Tre = ec * Dre + es * Dim;
            float Tim = ec * Dim - es * Dre;
            float nSre = L.z * Sre - L.w * Tre;
            float nSim = L.z * Sim - L.w * Tim;
            float nDre = L.w * Sre - L.z * Tre;
            float nDim = L.w * Sim - L.z * Tim;
            Sre = nSre; Sim = nSim; Dre = nDre; Dim = nDim;
        }
        while (j >= 7) {
            #pragma unroll
            for (int k = 0; k < 8; ++k) {
                float4 L = sL[j - k];
                float arg = s * L.x;
                float e; asm("ex2.approx.ftz.f32 %0, %1;" : "=f"(e) : "f"(s * L.y));
                float sn, cs; __sincosf(arg, &sn, &cs);
                float ec = e * cs, es = e * sn;
                float Tre = ec * Dre + es * Dim;
                float Tim = ec * Dim - es * Dre;
                float nSre = L.z * Sre - L.w * Tre;
                float nSim = L.z * Sim - L.w * Tim;
                float nDre = L.w * Sre - L.z * Tre;
                float nDim = L.w * Sim - L.z * Tim;
                Sre = nSre; Sim = nSim; Dre = nDre; Dim = nDim;
            }
            j -= 8;
            // exact pow2 renorm (common factor cancels in y = (S+D)/(S-D))
            float m1 = fmaxf(fabsf(Sre), fabsf(Sim));
            float m2 = fmaxf(fabsf(Dre), fabsf(Dim));
            float m = fmaxf(fmaxf(m1, m2), 1e-30f);
            unsigned eb = __float_as_uint(m) & 0x7f800000u;
            float sc = __uint_as_float(0x7f000000u - eb);
            Sre *= sc; Sim *= sc; Dre *= sc; Dim *= sc;
        }

        // y = (S+D)/(S-D); Z = y * Z_L0, |Z_L0|^2 = omu*rho0, arg = 45 deg
        float nre = Sre + Dre, nim = Sim + Dim;   // 2y * c
        float dre = Sre - Dre, dim = Sim - Dim;   // 2  * c
        float dd = dre * dre + dim * dim;
        float app_res = s_rho0 * (nre * nre + nim * nim) / dd;
        float yr = nre * dre + nim * dim;         // Re(y)*dd (scale cancels in atan2)
        float yi = nim * dre - nre * dim;         // Im(y)*dd
        float dl = log10f(app_res) - log10f(obs_r[i]);
        t1 = dl * dl;
        float ph = atan2f(yi, yr) * RAD2DEG_F + 45.0f;
        float dp = ph - obs_p[i];
        t2 = dp * dp;
    }

    // deterministic block reduction
    float x = t1, y = t2;
    #pragma unroll
    for (int o = 16; o > 0; o >>= 1) {
        x += __shfl_down_sync(0xffffffffu, x, o);
        y += __shfl_down_sync(0xffffffffu, y, o);
    }
    __shared__ float2 ws[4];
    int w = tid >> 5, l = tid & 31;
    if (l == 0) ws[w] = make_float2(x, y);
    __syncthreads();
    if (w == 0) {
        float2 vv = (l < ((int)blockDim.x >> 5)) ? ws[l] : make_float2(0.f, 0.f);
        #pragma unroll
        for (int o = 2; o > 0; o >>= 1) {
            vv.x += __shfl_down_sync(0xffffffffu, vv.x, o);
            vv.y += __shfl_down_sync(0xffffffffu, vv.y, o);
        }
        if (l == 0) g_part[blockIdx.x] = vv;
    }

    // last-block final reduction (fence + ticket; reset keeps replays valid)
    __threadfence();
    if (tid == 0) {
        unsigned t = atomicAdd(&g_ticket, 1u);
        s_last = (t == gridDim.x - 1u);
    }
    __syncthreads();
    if (s_last) {
        int nb = gridDim.x;
        float fx = 0.f, fy = 0.f;
        for (int b = tid; b < nb; b += blockDim.x) {
            float2 p = g_part[b];
            fx += p.x; fy += p.y;
        }
        #pragma unroll
        for (int o = 16; o > 0; o >>= 1) {
            fx += __shfl_down_sync(0xffffffffu, fx, o);
            fy += __shfl_down_sync(0xffffffffu, fy, o);
        }
        __shared__ float2 ws2[4];
        if (l == 0) ws2[w] = make_float2(fx, fy);
        __syncthreads();
        if (tid == 0) {
            float gx = 0.f, gy = 0.f;
            int nw = (int)blockDim.x >> 5;
            for (int q = 0; q < nw; ++q) { gx += ws2[q].x; gy += ws2[q].y; }
            float lr = gx * invnf;
            float lp = gy * invnf;
            out[0] = lr + 10.f * lp;
            out[1] = lr;
            out[2] = lp;
            g_ticket = 0u;   // reset for next graph replay
        }
    }
}

extern "C" void kernel_launch(void* const* d_in, const int* in_sizes, int n_in,
                              void* d_out, int out_size)
{
    const float* rho    = (const float*)d_in[0];
    const float* thick  = (const float*)d_in[1];
    const float* freq   = (const float*)d_in[2];
    const float* obs_r  = (const float*)d_in[3];
    const float* obs_p  = (const float*)d_in[4];
    int nz = in_sizes[0];
    int nf = in_sizes[2];
    int blocks = (nf + 127) / 128;
    if (blocks > 1024) blocks = 1024;  // g_part capacity (nf=16384 -> 128)
    mt_fused<<<blocks, 128>>>(rho, thick, freq, obs_r, obs_p,
                              (float*)d_out, nz, nf, 1.f / (float)nf);
}

// round 6
// speedup vs baseline: 1.3964x; 1.0267x over previous
#include <cuda_runtime.h>
#include <math.h>

// MT 1D forward + loss, single fused kernel — diagonalized recursion with
// TWO-WARP SPLIT per frequency for SMSP latency hiding.
//   Basis S = y+1, D = y-1 (y = Z/Zj): per layer
//     T = E*D ; S' = p*S - m*T ; D' = m*S - p*T,  p=(w+1)/2, m=(w-1)/2,
//     E = exp(-arg)*(cos arg - i sin arg), w = sqrt(rho_j/rho_{j-1}).
//   Vector warps (0-3) push the state through layers [nm .. nz-2].
//   Matrix warps (4-7) accumulate M = A_0*...*A_{nm-1} (2 columns, same step
//   applied to each). Combine v' = M*v once via shared memory.
//   Each SMSP gets one warp of each role -> stall bubbles of one warp are
//   filled by the other (the single-warp version idled 71% on MUFU chains).
// Exact pow2 renorm every 8 steps per warp; all scales cancel in the ratio.
// Loss reduction fused via fence + atomic ticket (reset for graph replay).

#define MU_F 1.2566370614359173e-6f
#define TWO_PI_F 6.283185307179586f
#define SQRT2_F 1.4142135623730951f
#define RAD2DEG_F 57.29577951308232f
#define NLOG2E_F (-1.4426950408889634f)

static __device__ float2 g_part[1024];
static __device__ unsigned g_ticket;   // zero-init; last block resets to 0

// E = ec - i*es from layer record
__device__ __forceinline__ void mk_e(float s, float4 L, float& ec, float& es)
{
    float arg = s * L.x;
    float e; asm("ex2.approx.ftz.f32 %0, %1;" : "=f"(e) : "f"(s * L.y));
    float sn, cs; __sincosf(arg, &sn, &cs);
    ec = e * cs; es = e * sn;
}

// one layer applied to a 2-component complex column (S-comp, D-comp)
__device__ __forceinline__ void step_col(float p, float m, float ec, float es,
    float& Sre, float& Sim, float& Dre, float& Dim)
{
    float Tre = ec * Dre + es * Dim;
    float Tim = ec * Dim - es * Dre;
    float nSre = p * Sre - m * Tre;
    float nSim = p * Sim - m * Tim;
    float nDre = m * Sre - p * Tre;
    float nDim = m * Sim - p * Tim;
    Sre = nSre; Sim = nSim; Dre = nDre; Dim = nDim;
}

__device__ __forceinline__ float pow2_scale(float m0)
{
    float m = fmaxf(m0, 1e-30f);
    unsigned eb = __float_as_uint(m) & 0x7f800000u;
    return __uint_as_float(0x7f000000u - eb);
}

__global__ __launch_bounds__(256, 1) void mt_fused(
    const float* __restrict__ rho, const float* __restrict__ thick,
    const float* __restrict__ freq, const float* __restrict__ obs_r,
    const float* __restrict__ obs_p, float* __restrict__ out,
    int nz, int nf, float invnf)
{
    // Layer record: x = sqrt2*t/sqrt(rho), y = -log2e*x, z = p, w = m
    __shared__ float4 sL[512];
    __shared__ float4 sM[128][4];      // per-freq 2x2 complex M (16 floats)
    __shared__ float s_y0, s_rho0;
    __shared__ int s_last;

    const int tid = threadIdx.x;
    for (int j = tid; j < nz - 1; j += blockDim.x) {
        float r = rho[j];
        float T = SQRT2_F * thick[j] * rsqrtf(r);
        float w = (j > 0) ? sqrtf(r / rho[j - 1]) : 1.0f;
        sL[j] = make_float4(T, NLOG2E_F * T, 0.5f * (w + 1.f), 0.5f * (w - 1.f));
    }
    if (tid == 0) {
        s_y0 = sqrtf(rho[nz - 1] / rho[nz - 2]);
        s_rho0 = rho[0];
    }
    __syncthreads();

    const int slot = tid & 127;            // frequency slot within block
    const int role = tid >> 7;             // 0 = vector warps, 1 = matrix warps
    int i = blockIdx.x * 128 + slot;
    const bool valid = (i < nf);
    if (i >= nf) i = nf - 1;               // clamp: keep execution uniform

    const float omu = TWO_PI_F * freq[i] * MU_F;
    const float s = sqrtf(omu);

    const int nL = nz - 1;                 // total layers (applied j=nL-1..0)
    const int nm = nL >> 1;                // matrix warps: layers j = nm-1..0

    if (role == 0) {
        // ---- vector half: v <- A_j * v for j = nL-1 .. nm ----
        float y0 = s_y0;
        float Sre = y0 + 1.f, Sim = 0.f, Dre = y0 - 1.f, Dim = 0.f;
        int j = nL - 1;
        int cnt = nL - nm;
        int rem = cnt & 7;
        #pragma unroll 1
        for (int k = 0; k < rem; ++k, --j) {
            float4 L = sL[j]; float ec, es; mk_e(s, L, ec, es);
            step_col(L.z, L.w, ec, es, Sre, Sim, Dre, Dim);
        }
        cnt -= rem;
        while (cnt > 0) {
            #pragma unroll
            for (int k = 0; k < 8; ++k) {
                float4 L = sL[j - k]; float ec, es; mk_e(s, L, ec, es);
                step_col(L.z, L.w, ec, es, Sre, Sim, Dre, Dim);
            }
            j -= 8; cnt -= 8;
            float sc = pow2_scale(fmaxf(fmaxf(fabsf(Sre), fabsf(Sim)),
                                        fmaxf(fabsf(Dre), fabsf(Dim))));
            Sre *= sc; Sim *= sc; Dre *= sc; Dim *= sc;
        }
        __syncthreads();                   // wait for matrix warps' M

        // v' = M * v
        float4 c1a = sM[slot][0], c1b = sM[slot][1];  // col1: m11, m21
        float4 c2a = sM[slot][2], c2b = sM[slot][3];  // col2: m12, m22
        float fSre = c1a.x * Sre - c1a.y * Sim + c2a.x * Dre - c2a.y * Dim;
        float fSim = c1a.x * Sim + c1a.y * Sre + c2a.x * Dim + c2a.y * Dre;
        float fDre = c1b.x * Sre - c1b.y * Sim + c2b.x * Dre - c2b.y * Dim;
        float fDim = c1b.x * Sim + c1b.y * Sre + c2b.x * Dim + c2b.y * Dre;

        // y = (S+D)/(S-D); Z = y*Z_L0, |Z_L0|^2 = omu*rho0, arg(Z_L0)=45deg
        float nre = fSre + fDre, nim = fSim + fDim;
        float dre = fSre - fDre, dim = fSim - fDim;
        float dd = dre * dre + dim * dim;
        float app_res = s_rho0 * (nre * nre + nim * nim) / dd;
        float yr = nre * dre + nim * dim;
        float yi = nim * dre - nre * dim;
        float t1 = 0.f, t2 = 0.f;
        if (valid) {
            float dl = log10f(app_res) - log10f(obs_r[i]);
            t1 = dl * dl;
            float ph = atan2f(yi, yr) * RAD2DEG_F + 45.0f;
            float dp = ph - obs_p[i];
            t2 = dp * dp;
        }
        // stash into registers reused below via shared path: fallthrough
        // (reduction is after the if/else join)
        sM[slot][0].x = t1;  sM[slot][0].y = t2;   // reuse smem as scratch
    } else {
        // ---- matrix half: M <- A_j * M for j = nm-1 .. 0 ----
        float aSre = 1.f, aSim = 0.f, aDre = 0.f, aDim = 0.f;  // col1 (m11,m21)
        float bSre = 0.f, bSim = 0.f, bDre = 1.f, bDim = 0.f;  // col2 (m12,m22)
        int j = nm - 1;
        int cnt = nm;
        int rem = cnt & 7;
        #pragma unroll 1
        for (int k = 0; k < rem; ++k, --j) {
            float4 L = sL[j]; float ec, es; mk_e(s, L, ec, es);
            step_col(L.z, L.w, ec, es, aSre, aSim, aDre, aDim);
            step_col(L.z, L.w, ec, es, bSre, bSim, bDre, bDim);
        }
        cnt -= rem;
        while (cnt > 0) {
            #pragma unroll
            for (int k = 0; k < 8; ++k) {
                float4 L = sL[j - k]; float ec, es; mk_e(s, L, ec, es);
                step_col(L.z, L.w, ec, es, aSre, aSim, aDre, aDim);
                step_col(L.z, L.w, ec, es, bSre, bSim, bDre, bDim);
            }
            j -= 8; cnt -= 8;
            float m1 = fmaxf(fmaxf(fabsf(aSre), fabsf(aSim)),
                             fmaxf(fabsf(aDre), fabsf(aDim)));
            float m2 = fmaxf(fmaxf(fabsf(bSre), fabsf(bSim)),
                             fmaxf(fabsf(bDre), fabsf(bDim)));
            float sc = pow2_scale(fmaxf(m1, m2));
            aSre *= sc; aSim *= sc; aDre *= sc; aDim *= sc;
            bSre *= sc; bSim *= sc; bDre *= sc; bDim *= sc;
        }
        sM[slot][0] = make_float4(aSre, aSim, 0.f, 0.f);   // m11
        sM[slot][1] = make_float4(aDre, aDim, 0.f, 0.f);   // m21
        sM[slot][2] = make_float4(bSre, bSim, 0.f, 0.f);   // m12
        sM[slot][3] = make_float4(bDre, bDim, 0.f, 0.f);   // m22
        __syncthreads();                   // publish M / wait with vector warps
    }

    __syncthreads();                       // t1/t2 scratch visible
    float x = (role == 0) ? sM[slot][0].x : 0.f;
    float y = (role == 0) ? sM[slot][0].y : 0.f;
    // NOTE: role-0 threads just wrote their own slot; re-read is exact.

    // deterministic block reduction (8 warps)
    #pragma unroll
    for (int o = 16; o > 0; o >>= 1) {
        x += __shfl_down_sync(0xffffffffu, x, o);
        y += __shfl_down_sync(0xffffffffu, y, o);
    }
    __shared__ float2 ws[8];
    int w = tid >> 5, l = tid & 31;
    if (l == 0) ws[w] = make_float2(x, y);
    __syncthreads();
    if (w == 0) {
        float2 vv = (l < 8) ? ws[l] : make_float2(0.f, 0.f);
        #pragma unroll
        for (int o = 4; o > 0; o >>= 1) {
            vv.x += __shfl_down_sync(0xffffffffu, vv.x, o);
            vv.y += __shfl_down_sync(0xffffffffu, vv.y, o);
        }
        if (l == 0) g_part[blockIdx.x] = vv;
    }

    // last-block final reduction (fence + ticket; reset keeps replays valid)
    __threadfence();
    if (tid == 0) {
        unsigned t = atomicAdd(&g_ticket, 1u);
        s_last = (t == gridDim.x - 1u);
    }
    __syncthreads();
    if (s_last) {
        int nb = gridDim.x;
        float fx = 0.f, fy = 0.f;
        for (int b = tid; b < nb; b += blockDim.x) {
            float2 p = g_part[b];
            fx += p.x; fy += p.y;
        }
        #pragma unroll
        for (int o = 16; o > 0; o >>= 1) {
            fx += __shfl_down_sync(0xffffffffu, fx, o);
            fy += __shfl_down_sync(0xffffffffu, fy, o);
        }
        __shared__ float2 ws2[8];
        if (l == 0) ws2[w] = make_float2(fx, fy);
        __syncthreads();
        if (tid == 0) {
            float gx = 0.f, gy = 0.f;
            int nw = (int)blockDim.x >> 5;
            for (int q = 0; q < nw; ++q) { gx += ws2[q].x; gy += ws2[q].y; }
            float lr = gx * invnf;
            float lp = gy * invnf;
            out[0] = lr + 10.f * lp;
            out[1] = lr;
            out[2] = lp;
            g_ticket = 0u;   // reset for next graph replay
        }
    }
}

extern "C" void kernel_launch(void* const* d_in, const int* in_sizes, int n_in,
                              void* d_out, int out_size)
{
    const float* rho    = (const float*)d_in[0];
    const float* thick  = (const float*)d_in[1];
    const float* freq   = (const float*)d_in[2];
    const float* obs_r  = (const float*)d_in[3];
    const float* obs_p  = (const float*)d_in[4];
    int nz = in_sizes[0];
    int nf = in_sizes[2];
    int blocks = (nf + 127) / 128;     // 128 freqs per block (256 threads)
    if (blocks > 1024) blocks = 1024;  // g_part capacity (nf=16384 -> 128)
    mt_fused<<<blocks, 256>>>(rho, thick, freq, obs_r, obs_p,
                              (float*)d_out, nz, nf, 1.f / (float)nf);
}